// round 6
// baseline (speedup 1.0000x reference)
#include <cuda_runtime.h>
#include <math.h>

// ---------------- configuration ----------------
#define THREADS 256
#define RPT 8                // rows per thread (4 packed row-pairs)
#define NPAIR (RPT / 2)
#define RB (THREADS * RPT)   // rows per block = 2048
#define CTILE 256            // columns per block tile (== THREADS)
#define MAXP 16384
#define MAXCH 64             // col chunks (12288/256 = 48)
#define MAXSL 64             // row slices (6 blocks * 8 warps = 48)

// ---------------- device scratch (race-free, fully overwritten) ----------------
__device__ float g_rpart[MAXCH][MAXP];  // [col-chunk][row] : min d^2 over chunk
__device__ float g_cpart[MAXSL][MAXP];  // [row-slice][col] : min d^2 over slice
__device__ float g_bsum[2][64];

// ---------------- packed f32x2 helpers ----------------
typedef unsigned long long ull;

__device__ __forceinline__ ull pack2(float x, float y) {
    ull r;
    asm("mov.b64 %0, {%1, %2};" : "=l"(r) : "f"(x), "f"(y));
    return r;
}
__device__ __forceinline__ void unpack2(ull v, float& x, float& y) {
    asm("mov.b64 {%0, %1}, %2;" : "=f"(x), "=f"(y) : "l"(v));
}
__device__ __forceinline__ ull fma2(ull a, ull b, ull c) {
    ull d;
    asm("fma.rn.f32x2 %0, %1, %2, %3;" : "=l"(d) : "l"(a), "l"(b), "l"(c));
    return d;
}
__device__ __forceinline__ ull add2(ull a, ull b) {
    ull d;
    asm("add.rn.f32x2 %0, %1, %2;" : "=l"(d) : "l"(a), "l"(b));
    return d;
}

// ---------------- kernel 1: single-pass d^2 tile, dual min ----------------
// rows = true_pos (packed 2 rows per FFMA2 lane), cols = pred_pos (dup'd in smem).
//   d^2 = (|b|^2 - 2 a.b) + |a|^2   -- exact for both mins
__global__ void __launch_bounds__(THREADS, 3)
k_pairs(const float* __restrict__ tp, const float* __restrict__ pp,
        int N, int M) {
    // Per column j, smem holds duplicated packed operands:
    //   sB[j*8+0..7] = {bx,bx, by,by, bz,bz, sb,sb}
    __shared__ __align__(16) float sB[CTILE * 8];

    const int tid = threadIdx.x;
    const int lane = tid & 31;
    const int wid = tid >> 5;
    const int rbase = blockIdx.x * RB;

    // ---- stage column tile (one column per thread, pre-duplicated) ----
    {
        int col = blockIdx.y * CTILE + tid;
        float bx = 0.f, by = 0.f, bz = 0.f, sb = 3e37f;  // pad never wins a min
        if (col < M) {
            bx = pp[3 * col + 0];
            by = pp[3 * col + 1];
            bz = pp[3 * col + 2];
            sb = bx * bx + by * by + bz * bz;
        }
        sB[tid * 8 + 0] = bx; sB[tid * 8 + 1] = bx;
        sB[tid * 8 + 2] = by; sB[tid * 8 + 3] = by;
        sB[tid * 8 + 4] = bz; sB[tid * 8 + 5] = bz;
        sB[tid * 8 + 6] = sb; sB[tid * 8 + 7] = sb;
    }
    __syncthreads();

    // ---- row pairs: lanes (lo,hi) = rows (ra, rb); coords pre-scaled by -2 ----
    ull axx[NPAIR], ayy[NPAIR], azz[NPAIR], saa[NPAIR];
    #pragma unroll
    for (int p = 0; p < NPAIR; p++) {
        int ra = rbase + (2 * p) * THREADS + tid;
        int rb_ = rbase + (2 * p + 1) * THREADS + tid;
        int ia = (ra < N) ? ra : 0;
        int ib = (rb_ < N) ? rb_ : 0;
        float ax0 = tp[3 * ia + 0], ay0 = tp[3 * ia + 1], az0 = tp[3 * ia + 2];
        float ax1 = tp[3 * ib + 0], ay1 = tp[3 * ib + 1], az1 = tp[3 * ib + 2];
        float sa0 = ax0 * ax0 + ay0 * ay0 + az0 * az0;
        float sa1 = ax1 * ax1 + ay1 * ay1 + az1 * az1;
        axx[p] = pack2(-2.f * ax0, -2.f * ax1);
        ayy[p] = pack2(-2.f * ay0, -2.f * ay1);
        azz[p] = pack2(-2.f * az0, -2.f * az1);
        saa[p] = pack2(sa0, sa1);
    }

    float m[RPT];
    #pragma unroll
    for (int r = 0; r < RPT; r++) m[r] = 3e38f;

    const ulonglong2* __restrict__ pB = reinterpret_cast<const ulonglong2*>(sB);
    const int slice = blockIdx.x * (THREADS / 32) + wid;
    const int cbase = blockIdx.y * CTILE;

    // ---- main loop: one column per j, 8 rows (4 packed pairs) ----
    #pragma unroll 2
    for (int j = 0; j < CTILE; j++) {
        ulonglong2 v0 = pB[2 * j];      // (bx,bx),(by,by)  broadcast LDS.128
        ulonglong2 v1 = pB[2 * j + 1];  // (bz,bz),(sb,sb)
        float cm = 3e38f;
        #pragma unroll
        for (int p = 0; p < NPAIR; p++) {
            ull t = fma2(axx[p], v0.x, v1.y);
            t = fma2(ayy[p], v0.y, t);
            t = fma2(azz[p], v1.x, t);      // t = sb - 2 a.b
            ull tc = add2(t, saa[p]);       // tc = d^2 (exact)
            float c0, c1;
            unpack2(tc, c0, c1);
            m[2 * p]     = fminf(m[2 * p], c0);      // row mins
            m[2 * p + 1] = fminf(m[2 * p + 1], c1);
            cm = fminf(cm, fminf(c0, c1));           // col min over 2 rows
        }
        // warp-reduce col min over 32 lanes (256 rows per warp)
        #pragma unroll
        for (int o = 16; o > 0; o >>= 1)
            cm = fminf(cm, __shfl_xor_sync(0xFFFFFFFFu, cm, o));
        if (lane == 0)
            g_cpart[slice][cbase + j] = cm;
    }

    // ---- write row-min partials (coalesced, race-free: chunk = blockIdx.y) ----
    #pragma unroll
    for (int r = 0; r < RPT; r++) {
        int row = rbase + r * THREADS + tid;
        if (row < N)
            g_rpart[blockIdx.y][row] = m[r];
    }
}

// ---------------- kernel 2: reduce partials, distances, block sums ----------------
#define FTHREADS 256
__global__ void k_final(int N, int M, int nch, int nsl, float* __restrict__ out) {
    const int dir = blockIdx.y;
    const int i = blockIdx.x * FTHREADS + threadIdx.x;

    float dist = 0.f;
    if (dir == 0) {
        if (i < N) {
            float v = 3e38f;
            for (int c = 0; c < nch; c++)
                v = fminf(v, g_rpart[c][i]);
            dist = sqrtf(fmaxf(v, 0.0f));
        }
    } else {
        if (i < M) {
            float v = 3e38f;
            for (int s = 0; s < nsl; s++)
                v = fminf(v, g_cpart[s][i]);
            dist = sqrtf(fmaxf(v, 0.0f));
            out[1 + i] = dist;  // mins_seeds
        }
    }

    __shared__ float red[FTHREADS];
    red[threadIdx.x] = dist;
    __syncthreads();
    for (int s = FTHREADS / 2; s > 0; s >>= 1) {
        if (threadIdx.x < s) red[threadIdx.x] += red[threadIdx.x + s];
        __syncthreads();
    }
    if (threadIdx.x == 0) g_bsum[dir][blockIdx.x] = red[0];
}

// ---------------- kernel 3: final sums + scalars ----------------
__global__ void k_out(int N, int M, int nb, float* __restrict__ out) {
    __shared__ float s[128];
    int t = threadIdx.x;  // blockDim = 64
    s[t]      = (t < nb) ? g_bsum[0][t] : 0.f;
    s[64 + t] = (t < nb) ? g_bsum[1][t] : 0.f;
    __syncthreads();
    #pragma unroll
    for (int st = 32; st > 0; st >>= 1) {
        if (t < st) {
            s[t] += s[t + st];
            s[64 + t] += s[64 + t + st];
        }
        __syncthreads();
    }
    if (t == 0) {
        float loss = s[0] / (float)N;
        float loss_seeds = s[64] / (float)M;
        out[0] = loss + loss_seeds;
        out[1 + M] = loss;
        out[2 + M] = loss_seeds;
    }
}

// ---------------- launch ----------------
extern "C" void kernel_launch(void* const* d_in, const int* in_sizes, int n_in,
                              void* d_out, int out_size) {
    const float* tp = (const float*)d_in[0];
    const float* pp = (const float*)d_in[1];
    float* out = (float*)d_out;
    const int N = in_sizes[0] / 3;
    const int M = in_sizes[1] / 3;
    const int maxP = (N > M) ? N : M;

    const int bx = (N + RB - 1) / RB;         // 6 row blocks
    const int nch = (M + CTILE - 1) / CTILE;  // 48 col chunks
    const int nsl = bx * (THREADS / 32);      // 48 row slices

    dim3 g1(bx, nch);                          // 288 blocks, 3 CTAs/SM, 1 wave
    k_pairs<<<g1, THREADS>>>(tp, pp, N, M);

    const int nb = (maxP + FTHREADS - 1) / FTHREADS;  // 48
    dim3 g2(nb, 2);
    k_final<<<g2, FTHREADS>>>(N, M, nch, nsl, out);

    k_out<<<1, 64>>>(N, M, nb, out);
}

// round 7
// speedup vs baseline: 1.3235x; 1.3235x over previous
#include <cuda_runtime.h>
#include <math.h>

// ---------------- configuration ----------------
#define THREADS 256
#define RPT 8                // rows per thread (4 packed row-pairs)
#define NPAIR (RPT / 2)
#define RB (THREADS * RPT)   // rows per block = 2048
#define CTILE 256            // columns per block tile (== THREADS)
#define MAXP 16384
#define MAXCH 64             // col chunks (12288/256 = 48)
#define MAXSL 64             // row slices (6 blocks * 8 warps = 48)

// ---------------- device scratch (race-free, fully overwritten) ----------------
__device__ float g_rpart[MAXCH][MAXP];  // [col-chunk][row] : min (d^2 + 1) over chunk
__device__ float g_cpart[MAXSL][MAXP];  // [row-slice][col] : min (d^2 + 1) over slice
__device__ float g_bsum[2][64];

// ---------------- packed f32x2 helpers ----------------
typedef unsigned long long ull;

__device__ __forceinline__ ull pack2(float x, float y) {
    ull r;
    asm("mov.b64 %0, {%1, %2};" : "=l"(r) : "f"(x), "f"(y));
    return r;
}
__device__ __forceinline__ void unpack2(ull v, float& x, float& y) {
    asm("mov.b64 {%0, %1}, %2;" : "=f"(x), "=f"(y) : "l"(v));
}
__device__ __forceinline__ ull fma2(ull a, ull b, ull c) {
    ull d;
    asm("fma.rn.f32x2 %0, %1, %2, %3;" : "=l"(d) : "l"(a), "l"(b), "l"(c));
    return d;
}
__device__ __forceinline__ ull add2(ull a, ull b) {
    ull d;
    asm("add.rn.f32x2 %0, %1, %2;" : "=l"(d) : "l"(a), "l"(b));
    return d;
}
// warp-wide unsigned min in one instruction (sm_80+)
__device__ __forceinline__ unsigned redux_min_u32(unsigned v) {
    unsigned d;
    asm("redux.sync.min.u32 %0, %1, 0xFFFFFFFF;" : "=r"(d) : "r"(v));
    return d;
}

// ---------------- kernel 1: single-pass (d^2+1) tile, dual min ----------------
// rows = true_pos (2 rows packed per FFMA2 lane), cols = pred_pos (dup'd smem).
//   tc = (|b|^2 - 2 a.b) + (|a|^2 + 1) = d^2 + 1  >= ~1  (positive -> uint order)
__global__ void __launch_bounds__(THREADS, 3)
k_pairs(const float* __restrict__ tp, const float* __restrict__ pp,
        int N, int M) {
    // Per column j: sB[j*8..] = {bx,bx, by,by, bz,bz, sb,sb}
    __shared__ __align__(16) float sB[CTILE * 8];

    const int tid = threadIdx.x;
    const int lane = tid & 31;
    const int wid = tid >> 5;
    const int rbase = blockIdx.x * RB;

    // ---- stage column tile (one column per thread, pre-duplicated) ----
    {
        int col = blockIdx.y * CTILE + tid;
        float bx = 0.f, by = 0.f, bz = 0.f, sb = 3e37f;  // pad never wins a min
        if (col < M) {
            bx = pp[3 * col + 0];
            by = pp[3 * col + 1];
            bz = pp[3 * col + 2];
            sb = bx * bx + by * by + bz * bz;
        }
        sB[tid * 8 + 0] = bx; sB[tid * 8 + 1] = bx;
        sB[tid * 8 + 2] = by; sB[tid * 8 + 3] = by;
        sB[tid * 8 + 4] = bz; sB[tid * 8 + 5] = bz;
        sB[tid * 8 + 6] = sb; sB[tid * 8 + 7] = sb;
    }
    __syncthreads();

    // ---- row pairs: coords pre-scaled by -2; |a|^2 pre-biased by +1 ----
    ull axx[NPAIR], ayy[NPAIR], azz[NPAIR], saa[NPAIR];
    #pragma unroll
    for (int p = 0; p < NPAIR; p++) {
        int ra = rbase + (2 * p) * THREADS + tid;
        int rb_ = rbase + (2 * p + 1) * THREADS + tid;
        int ia = (ra < N) ? ra : 0;
        int ib = (rb_ < N) ? rb_ : 0;
        float ax0 = tp[3 * ia + 0], ay0 = tp[3 * ia + 1], az0 = tp[3 * ia + 2];
        float ax1 = tp[3 * ib + 0], ay1 = tp[3 * ib + 1], az1 = tp[3 * ib + 2];
        float sa0 = ax0 * ax0 + ay0 * ay0 + az0 * az0 + 1.0f;
        float sa1 = ax1 * ax1 + ay1 * ay1 + az1 * az1 + 1.0f;
        axx[p] = pack2(-2.f * ax0, -2.f * ax1);
        ayy[p] = pack2(-2.f * ay0, -2.f * ay1);
        azz[p] = pack2(-2.f * az0, -2.f * az1);
        saa[p] = pack2(sa0, sa1);
    }

    float m[RPT];
    #pragma unroll
    for (int r = 0; r < RPT; r++) m[r] = 3e38f;

    const ulonglong2* __restrict__ pB = reinterpret_cast<const ulonglong2*>(sB);
    const int slice = blockIdx.x * (THREADS / 32) + wid;
    const int cbase = blockIdx.y * CTILE;

    // ---- main loop: one column per j, 8 rows (4 packed pairs) ----
    #pragma unroll 4
    for (int j = 0; j < CTILE; j++) {
        ulonglong2 v0 = pB[2 * j];      // (bx,bx),(by,by)  broadcast LDS.128
        ulonglong2 v1 = pB[2 * j + 1];  // (bz,bz),(sb,sb)
        float cm = 3e38f;
        #pragma unroll
        for (int p = 0; p < NPAIR; p++) {
            ull t = fma2(axx[p], v0.x, v1.y);
            t = fma2(ayy[p], v0.y, t);
            t = fma2(azz[p], v1.x, t);      // sb - 2 a.b
            ull tc = add2(t, saa[p]);       // d^2 + 1  (positive)
            float c0, c1;
            unpack2(tc, c0, c1);
            m[2 * p]     = fminf(m[2 * p], c0);       // row mins
            m[2 * p + 1] = fminf(m[2 * p + 1], c1);
            cm = fminf(cm, fminf(c0, c1));            // col min (this thread)
        }
        // one-instruction warp reduction (uint order == float order, all > 0)
        unsigned wmin = redux_min_u32(__float_as_uint(cm));
        if (lane == 0)
            g_cpart[slice][cbase + j] = __uint_as_float(wmin);
    }

    // ---- write row-min partials (coalesced, race-free: chunk = blockIdx.y) ----
    #pragma unroll
    for (int r = 0; r < RPT; r++) {
        int row = rbase + r * THREADS + tid;
        if (row < N)
            g_rpart[blockIdx.y][row] = m[r];
    }
}

// ---------------- kernel 2: reduce partials, distances, block sums ----------------
#define FTHREADS 256
__global__ void k_final(int N, int M, int nch, int nsl, float* __restrict__ out) {
    const int dir = blockIdx.y;
    const int i = blockIdx.x * FTHREADS + threadIdx.x;

    float dist = 0.f;
    if (dir == 0) {
        if (i < N) {
            float v = 3e38f;
            for (int c = 0; c < nch; c++)
                v = fminf(v, g_rpart[c][i]);
            dist = sqrtf(fmaxf(v - 1.0f, 0.0f));   // remove +1 bias
        }
    } else {
        if (i < M) {
            float v = 3e38f;
            for (int s = 0; s < nsl; s++)
                v = fminf(v, g_cpart[s][i]);
            dist = sqrtf(fmaxf(v - 1.0f, 0.0f));
            out[1 + i] = dist;  // mins_seeds
        }
    }

    __shared__ float red[FTHREADS];
    red[threadIdx.x] = dist;
    __syncthreads();
    for (int s = FTHREADS / 2; s > 0; s >>= 1) {
        if (threadIdx.x < s) red[threadIdx.x] += red[threadIdx.x + s];
        __syncthreads();
    }
    if (threadIdx.x == 0) g_bsum[dir][blockIdx.x] = red[0];
}

// ---------------- kernel 3: final sums + scalars ----------------
__global__ void k_out(int N, int M, int nb, float* __restrict__ out) {
    __shared__ float s[128];
    int t = threadIdx.x;  // blockDim = 64
    s[t]      = (t < nb) ? g_bsum[0][t] : 0.f;
    s[64 + t] = (t < nb) ? g_bsum[1][t] : 0.f;
    __syncthreads();
    #pragma unroll
    for (int st = 32; st > 0; st >>= 1) {
        if (t < st) {
            s[t] += s[t + st];
            s[64 + t] += s[64 + t + st];
        }
        __syncthreads();
    }
    if (t == 0) {
        float loss = s[0] / (float)N;
        float loss_seeds = s[64] / (float)M;
        out[0] = loss + loss_seeds;
        out[1 + M] = loss;
        out[2 + M] = loss_seeds;
    }
}

// ---------------- launch ----------------
extern "C" void kernel_launch(void* const* d_in, const int* in_sizes, int n_in,
                              void* d_out, int out_size) {
    const float* tp = (const float*)d_in[0];
    const float* pp = (const float*)d_in[1];
    float* out = (float*)d_out;
    const int N = in_sizes[0] / 3;
    const int M = in_sizes[1] / 3;
    const int maxP = (N > M) ? N : M;

    const int bx = (N + RB - 1) / RB;         // 6 row blocks
    const int nch = (M + CTILE - 1) / CTILE;  // 48 col chunks
    const int nsl = bx * (THREADS / 32);      // 48 row slices

    dim3 g1(bx, nch);                          // 288 blocks, 3 CTAs/SM possible
    k_pairs<<<g1, THREADS>>>(tp, pp, N, M);

    const int nb = (maxP + FTHREADS - 1) / FTHREADS;  // 48
    dim3 g2(nb, 2);
    k_final<<<g2, FTHREADS>>>(N, M, nch, nsl, out);

    k_out<<<1, 64>>>(N, M, nb, out);
}

// round 8
// speedup vs baseline: 1.3814x; 1.0437x over previous
#include <cuda_runtime.h>
#include <math.h>

// ---------------- configuration ----------------
#define THREADS 256
#define RPT 8                // rows per thread (4 packed row-pairs)
#define NPAIR (RPT / 2)
#define RB (THREADS * RPT)   // rows per block = 2048
#define CTILE 256            // columns per block tile (== THREADS)
#define MAXP 16384
#define MAXCH 64             // col chunks (12288/256 = 48)
#define MAXSL 64             // row slices (6 blocks * 8 warps = 48)

// ---------------- device scratch (race-free, fully overwritten) ----------------
__device__ float g_rpart[MAXCH][MAXP];  // [col-chunk][row] : min (d^2+1) over chunk
__device__ float g_cpart[MAXSL][MAXP];  // [row-slice][col] : min (d^2+1) over slice
__device__ float g_bsum[2][64];

// ---------------- packed f32x2 helpers ----------------
typedef unsigned long long ull;

__device__ __forceinline__ ull pack2(float x, float y) {
    ull r;
    asm("mov.b64 %0, {%1, %2};" : "=l"(r) : "f"(x), "f"(y));
    return r;
}
__device__ __forceinline__ void unpack2(ull v, float& x, float& y) {
    asm("mov.b64 {%0, %1}, %2;" : "=f"(x), "=f"(y) : "l"(v));
}
__device__ __forceinline__ ull fma2(ull a, ull b, ull c) {
    ull d;
    asm("fma.rn.f32x2 %0, %1, %2, %3;" : "=l"(d) : "l"(a), "l"(b), "l"(c));
    return d;
}
__device__ __forceinline__ ull add2(ull a, ull b) {
    ull d;
    asm("add.rn.f32x2 %0, %1, %2;" : "=l"(d) : "l"(a), "l"(b));
    return d;
}
// 3-input min: ptxas fuses to FMNMX3 on sm_90+/sm_10x
__device__ __forceinline__ float fmin3(float a, float b, float c) {
    return fminf(a, fminf(b, c));
}
__device__ __forceinline__ unsigned redux_min_u32(unsigned v) {
    unsigned d;
    asm("redux.sync.min.u32 %0, %1, 0xFFFFFFFF;" : "=r"(d) : "r"(v));
    return d;
}

// ---------------- kernel 1: single-pass (d^2+1) tile, dual min ----------------
// rows = true_pos (2 rows packed per FFMA2 lane), cols = pred_pos (dup'd smem).
//   tc = (|b|^2 - 2 a.b) + (|a|^2 + 1) = d^2 + 1 >= ~1 (positive -> uint order)
__global__ void __launch_bounds__(THREADS, 3)
k_pairs(const float* __restrict__ tp, const float* __restrict__ pp,
        int N, int M) {
    // Per column j: sB[j*8..] = {bx,bx, by,by, bz,bz, sb,sb}
    __shared__ __align__(16) float sB[CTILE * 8];

    const int tid = threadIdx.x;
    const int lane = tid & 31;
    const int wid = tid >> 5;
    const int rbase = blockIdx.x * RB;

    // ---- stage column tile (one column per thread, pre-duplicated) ----
    {
        int col = blockIdx.y * CTILE + tid;
        float bx = 0.f, by = 0.f, bz = 0.f, sb = 3e37f;  // pad never wins a min
        if (col < M) {
            bx = pp[3 * col + 0];
            by = pp[3 * col + 1];
            bz = pp[3 * col + 2];
            sb = bx * bx + by * by + bz * bz;
        }
        sB[tid * 8 + 0] = bx; sB[tid * 8 + 1] = bx;
        sB[tid * 8 + 2] = by; sB[tid * 8 + 3] = by;
        sB[tid * 8 + 4] = bz; sB[tid * 8 + 5] = bz;
        sB[tid * 8 + 6] = sb; sB[tid * 8 + 7] = sb;
    }
    __syncthreads();

    // ---- row pairs: coords pre-scaled by -2; |a|^2 pre-biased by +1 ----
    ull axx[NPAIR], ayy[NPAIR], azz[NPAIR], saa[NPAIR];
    #pragma unroll
    for (int p = 0; p < NPAIR; p++) {
        int ra = rbase + (2 * p) * THREADS + tid;
        int rb_ = rbase + (2 * p + 1) * THREADS + tid;
        int ia = (ra < N) ? ra : 0;
        int ib = (rb_ < N) ? rb_ : 0;
        float ax0 = tp[3 * ia + 0], ay0 = tp[3 * ia + 1], az0 = tp[3 * ia + 2];
        float ax1 = tp[3 * ib + 0], ay1 = tp[3 * ib + 1], az1 = tp[3 * ib + 2];
        float sa0 = ax0 * ax0 + ay0 * ay0 + az0 * az0 + 1.0f;
        float sa1 = ax1 * ax1 + ay1 * ay1 + az1 * az1 + 1.0f;
        axx[p] = pack2(-2.f * ax0, -2.f * ax1);
        ayy[p] = pack2(-2.f * ay0, -2.f * ay1);
        azz[p] = pack2(-2.f * az0, -2.f * az1);
        saa[p] = pack2(sa0, sa1);
    }

    float m[RPT];
    #pragma unroll
    for (int r = 0; r < RPT; r++) m[r] = 3e38f;

    const ulonglong2* __restrict__ pB = reinterpret_cast<const ulonglong2*>(sB);
    const int slice = blockIdx.x * (THREADS / 32) + wid;
    const int cbase = blockIdx.y * CTILE;

    // ---- main loop: TWO columns per iteration, 8 rows (4 packed pairs) ----
    #pragma unroll 2
    for (int j = 0; j < CTILE / 2; j++) {
        ulonglong2 vA0 = pB[4 * j];      // col A: (bx,bx),(by,by)
        ulonglong2 vA1 = pB[4 * j + 1];  // col A: (bz,bz),(sb,sb)
        ulonglong2 vB0 = pB[4 * j + 2];  // col B
        ulonglong2 vB1 = pB[4 * j + 3];
        float cmA = 3e38f, cmB = 3e38f;
        #pragma unroll
        for (int p = 0; p < NPAIR; p++) {
            ull tA = fma2(axx[p], vA0.x, vA1.y);
            tA = fma2(ayy[p], vA0.y, tA);
            tA = fma2(azz[p], vA1.x, tA);
            ull tcA = add2(tA, saa[p]);          // d^2+1, col A, rows (2p,2p+1)
            ull tB = fma2(axx[p], vB0.x, vB1.y);
            tB = fma2(ayy[p], vB0.y, tB);
            tB = fma2(azz[p], vB1.x, tB);
            ull tcB = add2(tB, saa[p]);          // col B
            float A0, A1, B0, B1;
            unpack2(tcA, A0, A1);
            unpack2(tcB, B0, B1);
            m[2 * p]     = fmin3(m[2 * p], A0, B0);      // row mins (FMNMX3)
            m[2 * p + 1] = fmin3(m[2 * p + 1], A1, B1);
            cmA = fmin3(cmA, A0, A1);                    // col mins (FMNMX3)
            cmB = fmin3(cmB, B0, B1);
        }
        unsigned wA = redux_min_u32(__float_as_uint(cmA));
        unsigned wB = redux_min_u32(__float_as_uint(cmB));
        if (lane == 0) {
            int c = cbase + 2 * j;
            g_cpart[slice][c]     = __uint_as_float(wA);
            g_cpart[slice][c + 1] = __uint_as_float(wB);
        }
    }

    // ---- write row-min partials (coalesced, race-free: chunk = blockIdx.y) ----
    #pragma unroll
    for (int r = 0; r < RPT; r++) {
        int row = rbase + r * THREADS + tid;
        if (row < N)
            g_rpart[blockIdx.y][row] = m[r];
    }
}

// ---------------- kernel 2: reduce partials, distances, block sums ----------------
#define FTHREADS 256
__global__ void k_final(int N, int M, int nch, int nsl, float* __restrict__ out) {
    const int dir = blockIdx.y;
    const int i = blockIdx.x * FTHREADS + threadIdx.x;

    float dist = 0.f;
    if (dir == 0) {
        if (i < N) {
            float v = 3e38f;
            for (int c = 0; c < nch; c++)
                v = fminf(v, g_rpart[c][i]);
            dist = sqrtf(fmaxf(v - 1.0f, 0.0f));   // remove +1 bias
        }
    } else {
        if (i < M) {
            float v = 3e38f;
            for (int s = 0; s < nsl; s++)
                v = fminf(v, g_cpart[s][i]);
            dist = sqrtf(fmaxf(v - 1.0f, 0.0f));
            out[1 + i] = dist;  // mins_seeds
        }
    }

    __shared__ float red[FTHREADS];
    red[threadIdx.x] = dist;
    __syncthreads();
    for (int s = FTHREADS / 2; s > 0; s >>= 1) {
        if (threadIdx.x < s) red[threadIdx.x] += red[threadIdx.x + s];
        __syncthreads();
    }
    if (threadIdx.x == 0) g_bsum[dir][blockIdx.x] = red[0];
}

// ---------------- kernel 3: final sums + scalars ----------------
__global__ void k_out(int N, int M, int nb, float* __restrict__ out) {
    __shared__ float s[128];
    int t = threadIdx.x;  // blockDim = 64
    s[t]      = (t < nb) ? g_bsum[0][t] : 0.f;
    s[64 + t] = (t < nb) ? g_bsum[1][t] : 0.f;
    __syncthreads();
    #pragma unroll
    for (int st = 32; st > 0; st >>= 1) {
        if (t < st) {
            s[t] += s[t + st];
            s[64 + t] += s[64 + t + st];
        }
        __syncthreads();
    }
    if (t == 0) {
        float loss = s[0] / (float)N;
        float loss_seeds = s[64] / (float)M;
        out[0] = loss + loss_seeds;
        out[1 + M] = loss;
        out[2 + M] = loss_seeds;
    }
}

// ---------------- launch ----------------
extern "C" void kernel_launch(void* const* d_in, const int* in_sizes, int n_in,
                              void* d_out, int out_size) {
    const float* tp = (const float*)d_in[0];
    const float* pp = (const float*)d_in[1];
    float* out = (float*)d_out;
    const int N = in_sizes[0] / 3;
    const int M = in_sizes[1] / 3;
    const int maxP = (N > M) ? N : M;

    const int bx = (N + RB - 1) / RB;         // 6 row blocks
    const int nch = (M + CTILE - 1) / CTILE;  // 48 col chunks
    const int nsl = bx * (THREADS / 32);      // 48 row slices

    dim3 g1(bx, nch);                          // 288 blocks
    k_pairs<<<g1, THREADS>>>(tp, pp, N, M);

    const int nb = (maxP + FTHREADS - 1) / FTHREADS;  // 48
    dim3 g2(nb, 2);
    k_final<<<g2, FTHREADS>>>(N, M, nch, nsl, out);

    k_out<<<1, 64>>>(N, M, nb, out);
}